// round 5
// baseline (speedup 1.0000x reference)
#include <cuda_runtime.h>

// Problem constants
#define Nv    20000
#define Tt    32
#define Ee    640000
#define Cc    10
#define Kk    5
#define PADc  2
#define REP   4
#define GSTAT 160

// ---------------- static device scratch (no allocs allowed) ----------------
__device__ int   g_cnt[REP][Nv];    // replicated degree counters
__device__ int   g_cur[REP][Nv];    // replicated scatter cursors
__device__ int   g_row[Nv + 1];     // CSR row offsets
__device__ int   g_adj[Ee];         // CSR adjacency (src per dst)
__device__ float g_invdeg[Nv];
__device__ float g_xn[Nv * Tt];     // normalized x of current layer
__device__ float g_cm[Nv * Tt];     // per-node conv+max message
__device__ float g_x[Nv * Tt];      // layer-0 output buffer
__device__ float g_part[GSTAT * 64];
__device__ float g_mean[Tt];        // alpha * mean (subtract term)
__device__ float g_invn[Tt];        // sqrt(N)/||x - alpha*mean||
__device__ float g_opart[2500 * 3]; // per-block output partials
__device__ int   g_ticket[4];       // last-block tickets (0:stats l0, 1:stats l1, 2:out)

// ---------------- zero counters + tickets ----------------
__global__ __launch_bounds__(256) void zero_k() {
    int i = blockIdx.x * blockDim.x + threadIdx.x;
    if (i < REP * Nv) ((int*)g_cnt)[i] = 0;
    if (i < 4) g_ticket[i] = 0;
}

// ---------------- count (replicated to cut atomic contention) ----------------
__global__ __launch_bounds__(256) void count_k(const int* __restrict__ ei) {
    int e = blockIdx.x * blockDim.x + threadIdx.x;
    if (e < Ee) atomicAdd(&g_cnt[e & 3][ei[Ee + e]], 1);
}

// ---------------- single-block scan: row offsets + per-replica cursor bases --
__global__ __launch_bounds__(512) void scan_k() {
    const int NTH = 512, CH = 40;  // 512*40 = 20480 >= Nv
    int tid = threadIdx.x;
    int base = tid * CH;
    int s = 0;
#pragma unroll 8
    for (int i = 0; i < CH; i++) {
        int idx = base + i;
        if (idx < Nv)
            s += g_cnt[0][idx] + g_cnt[1][idx] + g_cnt[2][idx] + g_cnt[3][idx];
    }
    __shared__ int sh[NTH];
    sh[tid] = s;
    __syncthreads();
    for (int off = 1; off < NTH; off <<= 1) {
        int v = 0;
        if (tid >= off) v = sh[tid - off];
        __syncthreads();
        if (tid >= off) sh[tid] += v;
        __syncthreads();
    }
    int run = sh[tid] - s;  // exclusive prefix of this thread's chunk
#pragma unroll 4
    for (int i = 0; i < CH; i++) {
        int idx = base + i;
        if (idx < Nv) {
            int c0 = g_cnt[0][idx], c1 = g_cnt[1][idx];
            int c2 = g_cnt[2][idx], c3 = g_cnt[3][idx];
            int tot = c0 + c1 + c2 + c3;
            g_row[idx] = run;
            g_cur[0][idx] = run;
            g_cur[1][idx] = run + c0;
            g_cur[2][idx] = run + c0 + c1;
            g_cur[3][idx] = run + c0 + c1 + c2;
            g_invdeg[idx] = 1.0f / (float)(tot > 1 ? tot : 1);
            run += tot;
        }
    }
    if (tid == NTH - 1) g_row[Nv] = sh[NTH - 1];
}

// ---------------- scatter (replicated cursors) ----------------
__global__ __launch_bounds__(256) void scatter_k(const int* __restrict__ ei) {
    int e = blockIdx.x * blockDim.x + threadIdx.x;
    if (e < Ee) {
        int d = ei[Ee + e];
        int p = atomicAdd(&g_cur[e & 3][d], 1);
        g_adj[p] = ei[e];
    }
}

// ---------------- column stats + fused last-block finish ----------------
// use_gx: 0 -> read x input, 1 -> read g_x
__global__ __launch_bounds__(256) void stats_k(const float* __restrict__ x, int use_gx,
                                               const float* __restrict__ alpha, int tick) {
    const float* __restrict__ src = use_gx ? (const float*)g_x : x;
    int tid = threadIdx.x;
    int lane = tid & 31;
    int w = tid >> 5;  // 0..7
    int wg = blockIdx.x * 8 + w;
    float s = 0.f, q = 0.f;
    for (int n = wg; n < Nv; n += GSTAT * 8) {
        float v = src[n * Tt + lane];
        s += v;
        q = fmaf(v, v, q);
    }
    __shared__ float sh[8][64];
    sh[w][lane] = s;
    sh[w][32 + lane] = q;
    __syncthreads();
    if (w == 0) {
        float ss = 0.f, qq = 0.f;
#pragma unroll
        for (int i = 0; i < 8; i++) { ss += sh[i][lane]; qq += sh[i][32 + lane]; }
        g_part[blockIdx.x * 64 + lane] = ss;
        g_part[blockIdx.x * 64 + 32 + lane] = qq;
        __threadfence();
    }
    __syncthreads();

    // last-block finish (ticket pattern; fixed-order sums -> deterministic)
    __shared__ int is_last;
    if (tid == 0) is_last = (atomicAdd(&g_ticket[tick], 1) == GSTAT - 1) ? 1 : 0;
    __syncthreads();
    if (!is_last) return;
    __threadfence();

    __shared__ float shf[4 * 64];
    __shared__ float shtot[64];
    int v = tid & 63;
    int seg = tid >> 6;  // 0..3, 40 blocks each
    float p = 0.f;
    int b0 = seg * 40;
#pragma unroll 8
    for (int b = b0; b < b0 + 40; b++) p += g_part[b * 64 + v];
    shf[seg * 64 + v] = p;
    __syncthreads();
    if (tid < 64) shtot[tid] = shf[tid] + shf[64 + tid] + shf[128 + tid] + shf[192 + tid];
    __syncthreads();
    if (tid < Tt) {
        float sum = shtot[tid];
        float qsum = shtot[32 + tid];
        float m = sum / (float)Nv;
        float a = alpha[tid];
        // ||x - a*m||^2 = q + N*m^2*(a^2 - 2a)
        float nsq = qsum + (float)Nv * m * m * (a * a - 2.f * a);
        g_mean[tid] = a * m;
        g_invn[tid] = sqrtf((float)Nv) * rsqrtf(nsq);
    }
}

// ---------------- normalize + per-node conv/max (warp per node) ------------
__global__ __launch_bounds__(256) void normconv_k(const float* __restrict__ x, int use_gx,
                           const float* __restrict__ Wc,   // [C*K] this layer
                           const float* __restrict__ bc,   // [C]
                           const float* __restrict__ scale,
                           const float* __restrict__ shift) {
    const float* __restrict__ src = use_gx ? (const float*)g_x : x;
    int lane = threadIdx.x & 31;
    int node = (blockIdx.x * blockDim.x + threadIdx.x) >> 5;
    if (node >= Nv) return;

    float v = src[node * Tt + lane];
    v = fmaf((v - g_mean[lane]) * g_invn[lane], scale[lane], shift[lane]);
    g_xn[node * Tt + lane] = v;

    float win[Kk];
#pragma unroll
    for (int d = -PADc; d <= PADc; d++) {
        int si = lane + d;
        float u = __shfl_sync(0xffffffffu, v, si & 31);
        win[d + PADc] = (si >= 0 && si < Tt) ? u : 0.f;
    }

    float mx = -3.0e38f;
#pragma unroll
    for (int c = 0; c < Cc; c++) {
        float a = bc[c];
#pragma unroll
        for (int k = 0; k < Kk; k++) a = fmaf(win[k], Wc[c * Kk + k], a);
        mx = fmaxf(mx, a);
    }
    g_cm[node * Tt + lane] = mx;
}

// ---------------- gather-aggregate + update + ReLU --------------------------
// fuse_out=0: write g_x (layer 0). fuse_out=1: fused output head (layer 1),
// no g_x store; last block writes the 3 logits.
__global__ __launch_bounds__(256) void aggr_k(int fuse_out,
                                              const float* __restrict__ Wout,
                                              const float* __restrict__ bout,
                                              float* __restrict__ out) {
    int tid = threadIdx.x;
    int lane = tid & 31;
    int w = tid >> 5;
    int node = (blockIdx.x * blockDim.x + tid) >> 5;

    float v = 0.f;
    if (node < Nv) {
        int beg = g_row[node];
        int end = g_row[node + 1];
        float acc = 0.f;
        for (int i = beg; i < end; i += 32) {
            int id = (i + lane < end) ? g_adj[i + lane] : 0;
            int m = end - i;
            if (m > 32) m = 32;
#pragma unroll 4
            for (int j = 0; j < m; j++) {
                int s = __shfl_sync(0xffffffffu, id, j);
                acc += g_cm[s * Tt + lane];
            }
        }
        float aggr = acc * g_invdeg[node];
        v = fmaxf(0.5f * (g_xn[node * Tt + lane] + aggr), 0.f);
    }

    if (!fuse_out) {
        if (node < Nv) g_x[node * Tt + lane] = v;
        return;
    }

    // ---- fused output head: s_n = rowsum(v); partial p_j += Wout[j][n]*s_n
    float s = v;
#pragma unroll
    for (int off = 16; off > 0; off >>= 1) s += __shfl_down_sync(0xffffffffu, s, off);

    __shared__ float shp[8][3];
    if (lane == 0) {
        shp[w][0] = Wout[node] * s;
        shp[w][1] = Wout[Nv + node] * s;
        shp[w][2] = Wout[2 * Nv + node] * s;
    }
    __syncthreads();
    if (tid < 3) {
        float p = 0.f;
#pragma unroll
        for (int i = 0; i < 8; i++) p += shp[i][tid];
        g_opart[blockIdx.x * 3 + tid] = p;
        __threadfence();
    }
    __syncthreads();

    __shared__ int is_last;
    if (tid == 0) is_last = (atomicAdd(&g_ticket[2], 1) == gridDim.x - 1) ? 1 : 0;
    __syncthreads();
    if (!is_last) return;
    __threadfence();

    // reduce 2500*3 partials: 85 chunks x 3 outputs, fixed order
    __shared__ float shr[256];
    shr[tid] = 0.f;
    if (tid < 255) {
        int j = tid % 3;
        int chunk = tid / 3;            // 0..84
        int b0 = chunk * 30;
        int b1 = b0 + 30;
        if (b1 > 2500) b1 = 2500;
        float p = 0.f;
        for (int b = b0; b < b1; b++) p += g_opart[b * 3 + j];
        shr[tid] = p;
    }
    __syncthreads();
    if (tid < 3) {
        float p = bout[tid];
        for (int c = 0; c < 85; c++) p += shr[c * 3 + tid];
        out[tid] = p;
    }
}

// ---------------- launch ---------------------------------------------------
extern "C" void kernel_launch(void* const* d_in, const int* in_sizes, int n_in,
                              void* d_out, int out_size) {
    const float* x     = (const float*)d_in[0];  // [N,T]
    const float* convW = (const float*)d_in[1];  // [L,C,1,K]
    const float* convb = (const float*)d_in[2];  // [L,C]
    const float* alpha = (const float*)d_in[3];  // [L,T]
    const float* scale = (const float*)d_in[4];  // [L,T]
    const float* shift = (const float*)d_in[5];  // [L,T]
    const float* Wout  = (const float*)d_in[6];  // [3,N]
    const float* bout  = (const float*)d_in[7];  // [3]
    const int*   ei    = (const int*)d_in[8];    // [2,E]
    float* out = (float*)d_out;

    const int nodeBlocks = Nv / 8;  // 2500: warp per node, 8 warps/block

    // CSR build (rebuilt every replay; atomics mutate counters/cursors)
    zero_k<<<(REP * Nv + 255) / 256, 256>>>();
    count_k<<<(Ee + 255) / 256, 256>>>(ei);
    scan_k<<<1, 512>>>();
    scatter_k<<<(Ee + 255) / 256, 256>>>(ei);

    // layer 0
    stats_k<<<GSTAT, 256>>>(x, 0, alpha, 0);
    normconv_k<<<nodeBlocks, 256>>>(x, 0, convW, convb, scale, shift);
    aggr_k<<<nodeBlocks, 256>>>(0, Wout, bout, out);

    // layer 1 (+ fused output head)
    stats_k<<<GSTAT, 256>>>(x, 1, alpha + Tt, 1);
    normconv_k<<<nodeBlocks, 256>>>(x, 1, convW + Cc * Kk, convb + Cc,
                                    scale + Tt, shift + Tt);
    aggr_k<<<nodeBlocks, 256>>>(1, Wout, bout, out);
}